// round 1
// baseline (speedup 1.0000x reference)
#include <cuda_runtime.h>
#include <math.h>

#define NN    32768
#define NE    262144
#define BG    32
#define NPG   1024
#define KSEL  820
#define HH    8
#define CC    64
#define HC    512
#define NEG   0.2f

// ------------------------- scratch (static device memory) -------------------------
__device__ float g_xl[(size_t)NN * HC];       // 64 MB
__device__ float g_xr[(size_t)NN * HC];       // 64 MB
__device__ float g_eproj[(size_t)NE * HC];    // 512 MB
__device__ float g_alpha[(size_t)NE * HH];    // 8 MB
__device__ float g_h[(size_t)NN * HC];        // 64 MB
__device__ float g_score[NN];
__device__ int   g_cnt[NN];
__device__ int   g_off[NN + 1];
__device__ int   g_cur[NN];
__device__ int   g_perm[NE];
__device__ int   g_sel[NN];
__device__ float g_rnorm;

// ------------------------- small utility kernels -------------------------
__global__ void k_rnorm(const float* __restrict__ pw) {
    __shared__ float s[512];
    int t = threadIdx.x;
    float v = pw[t];
    s[t] = v * v;
    __syncthreads();
    for (int off = 256; off > 0; off >>= 1) {
        if (t < off) s[t] += s[t + off];
        __syncthreads();
    }
    if (t == 0) g_rnorm = rsqrtf(s[0]);
}

__global__ void k_zero() {
    int i = blockIdx.x * 256 + threadIdx.x;
    if (i < NN) g_cnt[i] = 0;
}

__global__ void k_count(const int* __restrict__ ei) {
    int e = blockIdx.x * 256 + threadIdx.x;
    if (e < NE) atomicAdd(&g_cnt[ei[NE + e]], 1);
}

__global__ void k_scan() {
    __shared__ int s[1024];
    int t = threadIdx.x;
    int base = t * 32;
    int loc[32];
    int sum = 0;
#pragma unroll
    for (int j = 0; j < 32; j++) { loc[j] = g_cnt[base + j]; sum += loc[j]; }
    s[t] = sum;
    __syncthreads();
    for (int off = 1; off < 1024; off <<= 1) {
        int v = (t >= off) ? s[t - off] : 0;
        __syncthreads();
        s[t] += v;
        __syncthreads();
    }
    int run = s[t] - sum;  // exclusive prefix
#pragma unroll
    for (int j = 0; j < 32; j++) {
        g_off[base + j] = run;
        g_cur[base + j] = run;
        run += loc[j];
    }
    if (t == 1023) g_off[NN] = run;
}

__global__ void k_scatter(const int* __restrict__ ei) {
    int e = blockIdx.x * 256 + threadIdx.x;
    if (e < NE) {
        int d = ei[NE + e];
        int p = atomicAdd(&g_cur[d], 1);
        g_perm[p] = e;
    }
}

// ------------------------- SGEMM: C[M,Nn] = A[M,K] @ B[K,Nn] (+bias) -------------------------
// BM=BN=128, BK=16, 256 threads, TM=TN=8. M,Nn multiples of 128; K multiple of 16.
// dst_sel: 0 -> g_xl, 1 -> g_xr, 2 -> g_eproj
__global__ void __launch_bounds__(256) sgemm16(const float* __restrict__ A,
                                               const float* __restrict__ B,
                                               const float* __restrict__ bias,
                                               int dst_sel, int M, int K, int Nn) {
    float* Cmat = (dst_sel == 0) ? g_xl : (dst_sel == 1) ? g_xr : g_eproj;
    __shared__ float As[16][128];
    __shared__ float Bs[16][128];
    int tid = threadIdx.x;
    int bm = blockIdx.x * 128;
    int bn = blockIdx.y * 128;
    int rm = (tid >> 4) * 8;
    int cn = (tid & 15) * 8;

    float acc[8][8];
#pragma unroll
    for (int i = 0; i < 8; i++)
#pragma unroll
        for (int j = 0; j < 8; j++) acc[i][j] = 0.f;

    for (int kt = 0; kt < K; kt += 16) {
        // load A tile 128x16 (512 float4)
#pragma unroll
        for (int i = 0; i < 2; i++) {
            int idx4 = tid + i * 256;
            int row = idx4 >> 2;
            int c4 = idx4 & 3;
            float4 v = *(const float4*)(A + (size_t)(bm + row) * K + kt + c4 * 4);
            As[c4 * 4 + 0][row] = v.x;
            As[c4 * 4 + 1][row] = v.y;
            As[c4 * 4 + 2][row] = v.z;
            As[c4 * 4 + 3][row] = v.w;
        }
        // load B tile 16x128 (512 float4)
#pragma unroll
        for (int i = 0; i < 2; i++) {
            int idx4 = tid + i * 256;
            int krow = idx4 >> 5;
            int c4 = idx4 & 31;
            *(float4*)(&Bs[krow][c4 * 4]) =
                *(const float4*)(B + (size_t)(kt + krow) * Nn + bn + c4 * 4);
        }
        __syncthreads();
#pragma unroll
        for (int k = 0; k < 16; k++) {
            float a[8], bb[8];
#pragma unroll
            for (int i = 0; i < 8; i++) a[i] = As[k][rm + i];
#pragma unroll
            for (int j = 0; j < 8; j++) bb[j] = Bs[k][cn + j];
#pragma unroll
            for (int i = 0; i < 8; i++)
#pragma unroll
                for (int j = 0; j < 8; j++) acc[i][j] = fmaf(a[i], bb[j], acc[i][j]);
        }
        __syncthreads();
    }
    // epilogue
#pragma unroll
    for (int i = 0; i < 8; i++) {
        size_t rowoff = (size_t)(bm + rm + i) * Nn + bn + cn;
#pragma unroll
        for (int j = 0; j < 8; j++) {
            float v = acc[i][j];
            if (bias) v += bias[bn + cn + j];
            Cmat[rowoff + j] = v;
        }
    }
}

// ------------------------- per-edge attention logits -------------------------
// alpha[e,h] = sum_c att[h,c] * leaky( xl[src,h,c] + xr[dst,h,c] + eproj[e,h,c] )
__global__ void __launch_bounds__(256) k_alpha(const int* __restrict__ ei,
                                               const float* __restrict__ att) {
    __shared__ float satt[HC];
    int tid = threadIdx.x;
    for (int i = tid; i < HC; i += 256) satt[i] = att[i];
    __syncthreads();

    int warp = tid >> 5, lane = tid & 31;
#pragma unroll 1
    for (int r = 0; r < 8; r++) {
        int e = blockIdx.x * 64 + warp * 8 + r;
        int src = ei[e];
        int dst = ei[NE + e];
        const float* pl = g_xl + (size_t)src * HC;
        const float* pr = g_xr + (size_t)dst * HC;
        const float* pe = g_eproj + (size_t)e * HC;
        float part[16];
#pragma unroll
        for (int t = 0; t < 16; t++) {
            int k = lane + 32 * t;
            float v = pl[k] + pr[k] + pe[k];
            v = (v > 0.f) ? v : NEG * v;
            part[t] = v * satt[k];
        }
#pragma unroll
        for (int h = 0; h < 8; h++) {
            float s = part[2 * h] + part[2 * h + 1];
            s += __shfl_xor_sync(0xffffffffu, s, 16);
            s += __shfl_xor_sync(0xffffffffu, s, 8);
            s += __shfl_xor_sync(0xffffffffu, s, 4);
            s += __shfl_xor_sync(0xffffffffu, s, 2);
            s += __shfl_xor_sync(0xffffffffu, s, 1);
            if (lane == 0) g_alpha[(size_t)e * 8 + h] = s;
        }
    }
}

// ------------------------- per-node: softmax + aggregation + bias/relu + score -------------------------
__global__ void __launch_bounds__(256) k_node(const int* __restrict__ ei,
                                              const float* __restrict__ bias,
                                              const float* __restrict__ pw) {
    int tid = threadIdx.x;
    int warp = tid >> 5, lane = tid & 31;
    int n = blockIdx.x * 8 + warp;
    int beg = g_off[n], end = g_off[n + 1];

    // pass 1: per-head max on lanes 0..7
    float m = -INFINITY;
    if (lane < 8) {
        for (int i = beg; i < end; i++) {
            int e = g_perm[i];
            m = fmaxf(m, g_alpha[(size_t)e * 8 + lane]);
        }
    }

    float acc[16];
#pragma unroll
    for (int t = 0; t < 16; t++) acc[t] = 0.f;
    float dsum = 0.f;

    // pass 2: exp weights + weighted aggregation of xl[src]
    for (int i = beg; i < end; i++) {
        int e = g_perm[i];
        int src = ei[e];
        float w = 0.f;
        if (lane < 8) {
            w = expf(g_alpha[(size_t)e * 8 + lane] - m);
            dsum += w;
        }
        const float* pl = g_xl + (size_t)src * HC;
#pragma unroll
        for (int t = 0; t < 16; t++) {
            int h = t >> 1;
            float wh = __shfl_sync(0xffffffffu, w, h);
            acc[t] = fmaf(wh, pl[lane + 32 * t], acc[t]);
        }
    }

    float invd = (lane < 8 && dsum > 0.f) ? 1.f / dsum : 0.f;

    // epilogue: scale by 1/denom, +bias, ReLU, store h, compute score dot
    float sc = 0.f;
#pragma unroll
    for (int t = 0; t < 16; t++) {
        int k = lane + 32 * t;
        int h = t >> 1;
        float id = __shfl_sync(0xffffffffu, invd, h);
        float y = acc[t] * id + bias[k];
        y = fmaxf(y, 0.f);
        g_h[(size_t)n * HC + k] = y;
        sc = fmaf(y, pw[k], sc);
    }
    sc += __shfl_xor_sync(0xffffffffu, sc, 16);
    sc += __shfl_xor_sync(0xffffffffu, sc, 8);
    sc += __shfl_xor_sync(0xffffffffu, sc, 4);
    sc += __shfl_xor_sync(0xffffffffu, sc, 2);
    sc += __shfl_xor_sync(0xffffffffu, sc, 1);
    if (lane == 0) g_score[n] = tanhf(sc * g_rnorm);
}

// ------------------------- top-K selection per graph (rank by comparison) -------------------------
__global__ void __launch_bounds__(1024) k_topk() {
    __shared__ float s[NPG];
    int b = blockIdx.x, t = threadIdx.x;
    float v = g_score[b * NPG + t];
    s[t] = v;
    __syncthreads();
    int rank = 0;
#pragma unroll 4
    for (int j = 0; j < NPG; j++) {
        float o = s[j];
        rank += (o > v) || (o == v && j < t);
    }
    g_sel[b * NPG + t] = (rank < KSEL) ? 1 : 0;
}

// ------------------------- global max pool || mean pool over selected rows -------------------------
__global__ void __launch_bounds__(512) k_pool(float* __restrict__ out) {
    __shared__ float sv[NPG];
    __shared__ int sf[NPG];
    int b = blockIdx.x, ch = threadIdx.x;
    for (int j = ch; j < NPG; j += 512) {
        sf[j] = g_sel[b * NPG + j];
        sv[j] = g_score[b * NPG + j];
    }
    __syncthreads();
    float mx = -INFINITY, sm = 0.f;
    for (int j = 0; j < NPG; j++) {
        if (sf[j]) {
            float p = sv[j] * g_h[(size_t)(b * NPG + j) * HC + ch];
            mx = fmaxf(mx, p);
            sm += p;
        }
    }
    out[b * 1024 + ch] = mx;
    out[b * 1024 + 512 + ch] = sm * (1.f / (float)KSEL);
}

// ------------------------- launch -------------------------
extern "C" void kernel_launch(void* const* d_in, const int* in_sizes, int n_in,
                              void* d_out, int out_size) {
    const float* x    = (const float*)d_in[0];
    const float* ea   = (const float*)d_in[1];
    const float* Wl   = (const float*)d_in[2];
    const float* bl   = (const float*)d_in[3];
    const float* Wr   = (const float*)d_in[4];
    const float* br   = (const float*)d_in[5];
    const float* We   = (const float*)d_in[6];
    const float* att  = (const float*)d_in[7];
    const float* bias = (const float*)d_in[8];
    const float* pw   = (const float*)d_in[9];
    const int*   ei   = (const int*)d_in[10];
    float* out = (float*)d_out;

    k_rnorm<<<1, 512>>>(pw);
    k_zero<<<128, 256>>>();
    k_count<<<1024, 256>>>(ei);
    k_scan<<<1, 1024>>>();
    k_scatter<<<1024, 256>>>(ei);

    // xl = x@Wl + bl ; xr = x@Wr + br
    sgemm16<<<dim3(NN / 128, HC / 128), 256>>>(x, Wl, bl, 0, NN, 256, HC);
    sgemm16<<<dim3(NN / 128, HC / 128), 256>>>(x, Wr, br, 1, NN, 256, HC);
    // eproj = edge_attr @ We
    sgemm16<<<dim3(NE / 128, HC / 128), 256>>>(ea, We, nullptr, 2, NE, 32, HC);

    k_alpha<<<NE / 64, 256>>>(ei, att);
    k_node<<<NN / 8, 256>>>(ei, bias, pw);
    k_topk<<<BG, 1024>>>();
    k_pool<<<BG, 512>>>(out);
}

// round 2
// speedup vs baseline: 1.7354x; 1.7354x over previous
#include <cuda_runtime.h>
#include <math.h>

#define NN    32768
#define NE    262144
#define BG    32
#define NPG   1024
#define KSEL  820
#define HH    8
#define CC    64
#define HC    512
#define NEG   0.2f

// ------------------------- scratch (static device memory) -------------------------
__device__ float g_xl[(size_t)NN * HC];       // 64 MB
__device__ float g_xr[(size_t)NN * HC];       // 64 MB
__device__ float g_alpha[(size_t)NE * HH];    // 8 MB
__device__ float g_h[(size_t)NN * HC];        // 64 MB
__device__ float g_score[NN];
__device__ int   g_cnt[NN];
__device__ int   g_off[NN + 1];
__device__ int   g_cur[NN];
__device__ int   g_perm[NE];
__device__ int   g_sel[NN];
__device__ int   g_bsum[32];
__device__ float g_rnorm;

// ------------------------- small utility kernels -------------------------
__global__ void k_rnorm(const float* __restrict__ pw) {
    __shared__ float s[512];
    int t = threadIdx.x;
    float v = pw[t];
    s[t] = v * v;
    __syncthreads();
    for (int off = 256; off > 0; off >>= 1) {
        if (t < off) s[t] += s[t + off];
        __syncthreads();
    }
    if (t == 0) g_rnorm = rsqrtf(s[0]);
}

__global__ void k_zero() {
    int i = blockIdx.x * 256 + threadIdx.x;
    if (i < NN) g_cnt[i] = 0;
}

__global__ void k_count(const int* __restrict__ ei) {
    int e = blockIdx.x * 256 + threadIdx.x;
    if (e < NE) atomicAdd(&g_cnt[ei[NE + e]], 1);
}

// ---- parallel exclusive scan over g_cnt[32768]: 3 phases ----
__global__ void __launch_bounds__(1024) k_scanA() {
    __shared__ int s[1024];
    int b = blockIdx.x, t = threadIdx.x, gi = b * 1024 + t;
    int v = g_cnt[gi];
    s[t] = v;
    __syncthreads();
    for (int off = 1; off < 1024; off <<= 1) {
        int u = (t >= off) ? s[t - off] : 0;
        __syncthreads();
        s[t] += u;
        __syncthreads();
    }
    g_off[gi] = s[t] - v;          // block-local exclusive
    if (t == 1023) g_bsum[b] = s[t];
}

__global__ void k_scanB() {
    int t = threadIdx.x;           // 32 threads
    int v = g_bsum[t];
    int x = v;
    for (int off = 1; off < 32; off <<= 1) {
        int u = __shfl_up_sync(0xffffffffu, x, off);
        if (t >= off) x += u;
    }
    g_bsum[t] = x - v;             // exclusive block offsets
}

__global__ void __launch_bounds__(1024) k_scanC() {
    int b = blockIdx.x, t = threadIdx.x, gi = b * 1024 + t;
    int o = g_off[gi] + g_bsum[b];
    g_off[gi] = o;
    g_cur[gi] = o;
    if (gi == NN - 1) g_off[NN] = NE;
}

__global__ void k_scatter(const int* __restrict__ ei) {
    int e = blockIdx.x * 256 + threadIdx.x;
    if (e < NE) {
        int d = ei[NE + e];
        int p = atomicAdd(&g_cur[d], 1);
        g_perm[p] = e;
    }
}

// ------------------------- SGEMM for xl & xr, double-buffered -------------------------
// C = x @ [Wl|Wr] + [bl|br]. grid = (NN/128, 8). by<4 -> Wl block by -> g_xl; else Wr -> g_xr.
// BM=BN=128, BK=16, 256 threads, TM=TN=8, ping-pong smem (1 sync / ktile).
__global__ void __launch_bounds__(256) sgemm_x(const float* __restrict__ A,
                                               const float* __restrict__ Wl,
                                               const float* __restrict__ bl,
                                               const float* __restrict__ Wr,
                                               const float* __restrict__ br) {
    __shared__ float As[2][16][132];
    __shared__ float Bs[2][16][132];
    const int by = blockIdx.y;
    const float* B    = (by < 4) ? Wl : Wr;
    const float* bias = (by < 4) ? bl : br;
    float* Cmat       = (by < 4) ? g_xl : g_xr;
    const int bn = (by & 3) * 128;
    const int bm = blockIdx.x * 128;
    const int tid = threadIdx.x;
    const int rm = (tid >> 4) * 8, cn = (tid & 15) * 8;
    const int K = 256, Nn = HC;

    float4 a_reg[2], b_reg[2];
    float acc[8][8];
#pragma unroll
    for (int i = 0; i < 8; i++)
#pragma unroll
        for (int j = 0; j < 8; j++) acc[i][j] = 0.f;

    // prologue: load tile 0
#pragma unroll
    for (int i = 0; i < 2; i++) {
        int idx4 = tid + i * 256;
        a_reg[i] = *(const float4*)(A + (size_t)(bm + (idx4 >> 2)) * K + (idx4 & 3) * 4);
        b_reg[i] = *(const float4*)(B + (size_t)(idx4 >> 5) * Nn + bn + (idx4 & 31) * 4);
    }
#pragma unroll
    for (int i = 0; i < 2; i++) {
        int idx4 = tid + i * 256;
        int row = idx4 >> 2, c4 = idx4 & 3;
        As[0][c4 * 4 + 0][row] = a_reg[i].x;
        As[0][c4 * 4 + 1][row] = a_reg[i].y;
        As[0][c4 * 4 + 2][row] = a_reg[i].z;
        As[0][c4 * 4 + 3][row] = a_reg[i].w;
        *(float4*)(&Bs[0][idx4 >> 5][(idx4 & 31) * 4]) = b_reg[i];
    }
    __syncthreads();

#pragma unroll 1
    for (int kt = 0; kt < 16; kt++) {
        int p = kt & 1;
        if (kt < 15) {
            int kb = (kt + 1) * 16;
#pragma unroll
            for (int i = 0; i < 2; i++) {
                int idx4 = tid + i * 256;
                a_reg[i] = *(const float4*)(A + (size_t)(bm + (idx4 >> 2)) * K + kb + (idx4 & 3) * 4);
                b_reg[i] = *(const float4*)(B + (size_t)(kb + (idx4 >> 5)) * Nn + bn + (idx4 & 31) * 4);
            }
        }
#pragma unroll
        for (int k = 0; k < 16; k++) {
            float a[8], bb[8];
            *(float4*)(a)      = *(float4*)(&As[p][k][rm]);
            *(float4*)(a + 4)  = *(float4*)(&As[p][k][rm + 4]);
            *(float4*)(bb)     = *(float4*)(&Bs[p][k][cn]);
            *(float4*)(bb + 4) = *(float4*)(&Bs[p][k][cn + 4]);
#pragma unroll
            for (int i = 0; i < 8; i++)
#pragma unroll
                for (int j = 0; j < 8; j++) acc[i][j] = fmaf(a[i], bb[j], acc[i][j]);
        }
        if (kt < 15) {
            int q = p ^ 1;
#pragma unroll
            for (int i = 0; i < 2; i++) {
                int idx4 = tid + i * 256;
                int row = idx4 >> 2, c4 = idx4 & 3;
                As[q][c4 * 4 + 0][row] = a_reg[i].x;
                As[q][c4 * 4 + 1][row] = a_reg[i].y;
                As[q][c4 * 4 + 2][row] = a_reg[i].z;
                As[q][c4 * 4 + 3][row] = a_reg[i].w;
                *(float4*)(&Bs[q][idx4 >> 5][(idx4 & 31) * 4]) = b_reg[i];
            }
            __syncthreads();
        }
    }

    // epilogue
    float bv[8];
    *(float4*)(bv)     = *(const float4*)(bias + bn + cn);
    *(float4*)(bv + 4) = *(const float4*)(bias + bn + cn + 4);
#pragma unroll
    for (int i = 0; i < 8; i++) {
        float o[8];
#pragma unroll
        for (int j = 0; j < 8; j++) o[j] = acc[i][j] + bv[j];
        float* dst = Cmat + (size_t)(bm + rm + i) * HC + bn + cn;
        *(float4*)(dst)     = *(float4*)(o);
        *(float4*)(dst + 4) = *(float4*)(o + 4);
    }
}

// ------------------------- fused eproj GEMM + attention logits -------------------------
// For a tile of 128 edges x 128 channels (= exactly 2 heads), compute
// eproj = edge_attr @ We in-register, add gathered xl[src]+xr[dst], leaky, dot att,
// reduce and write alpha[e, head] directly. grid = (NE/128, 4).
__global__ void __launch_bounds__(256) k_egemm_alpha(const float* __restrict__ EA,
                                                     const float* __restrict__ We,
                                                     const float* __restrict__ att,
                                                     const int* __restrict__ ei) {
    __shared__ float As[32][132];
    __shared__ float Bs[32][132];
    __shared__ int s_src[128];
    __shared__ int s_dst[128];
    const int tid = threadIdx.x;
    const int bm = blockIdx.x * 128;   // edge base
    const int bn = blockIdx.y * 128;   // channel base

    // load A tile: 128 edges x 32 attrs
#pragma unroll
    for (int i = 0; i < 4; i++) {
        int idx4 = tid + i * 256;
        int row = idx4 >> 3, c4 = idx4 & 7;
        float4 v = *(const float4*)(EA + (size_t)(bm + row) * 32 + c4 * 4);
        As[c4 * 4 + 0][row] = v.x;
        As[c4 * 4 + 1][row] = v.y;
        As[c4 * 4 + 2][row] = v.z;
        As[c4 * 4 + 3][row] = v.w;
    }
    // load B tile: 32 x 128
#pragma unroll
    for (int i = 0; i < 4; i++) {
        int idx4 = tid + i * 256;
        int krow = idx4 >> 5, c4 = idx4 & 31;
        *(float4*)(&Bs[krow][c4 * 4]) = *(const float4*)(We + (size_t)krow * HC + bn + c4 * 4);
    }
    if (tid < 128) s_src[tid] = ei[bm + tid];
    else           s_dst[tid - 128] = ei[NE + bm + tid - 128];
    __syncthreads();

    const int rm = (tid >> 4) * 8, cn = (tid & 15) * 8;
    float acc[8][8];
#pragma unroll
    for (int i = 0; i < 8; i++)
#pragma unroll
        for (int j = 0; j < 8; j++) acc[i][j] = 0.f;

#pragma unroll
    for (int k = 0; k < 32; k++) {
        float a[8], bb[8];
        *(float4*)(a)      = *(float4*)(&As[k][rm]);
        *(float4*)(a + 4)  = *(float4*)(&As[k][rm + 4]);
        *(float4*)(bb)     = *(float4*)(&Bs[k][cn]);
        *(float4*)(bb + 4) = *(float4*)(&Bs[k][cn + 4]);
#pragma unroll
        for (int i = 0; i < 8; i++)
#pragma unroll
            for (int j = 0; j < 8; j++) acc[i][j] = fmaf(a[i], bb[j], acc[i][j]);
    }

    // epilogue: alpha partials
    float ra[8];
    *(float4*)(ra)     = *(const float4*)(att + bn + cn);
    *(float4*)(ra + 4) = *(const float4*)(att + bn + cn + 4);
    const int head = (bn >> 6) + ((tid & 15) >> 3);

#pragma unroll
    for (int i = 0; i < 8; i++) {
        int er = rm + i;
        const float* pl = g_xl + (size_t)s_src[er] * HC + bn + cn;
        const float* pr = g_xr + (size_t)s_dst[er] * HC + bn + cn;
        float l[8], r[8];
        *(float4*)(l)     = *(const float4*)(pl);
        *(float4*)(l + 4) = *(const float4*)(pl + 4);
        *(float4*)(r)     = *(const float4*)(pr);
        *(float4*)(r + 4) = *(const float4*)(pr + 4);
        float s = 0.f;
#pragma unroll
        for (int j = 0; j < 8; j++) {
            float v = acc[i][j] + l[j] + r[j];
            v = (v > 0.f) ? v : NEG * v;
            s = fmaf(v, ra[j], s);
        }
        s += __shfl_xor_sync(0xffffffffu, s, 4);
        s += __shfl_xor_sync(0xffffffffu, s, 2);
        s += __shfl_xor_sync(0xffffffffu, s, 1);
        if ((tid & 7) == 0) g_alpha[(size_t)(bm + er) * 8 + head] = s;
    }
}

// ------------------------- per-node: softmax + aggregation + bias/relu + score -------------------------
__global__ void __launch_bounds__(256) k_node(const int* __restrict__ ei,
                                              const float* __restrict__ bias,
                                              const float* __restrict__ pw) {
    int tid = threadIdx.x;
    int warp = tid >> 5, lane = tid & 31;
    int n = blockIdx.x * 8 + warp;
    int beg = g_off[n], end = g_off[n + 1];

    float m = -INFINITY;
    if (lane < 8) {
        for (int i = beg; i < end; i++) {
            int e = g_perm[i];
            m = fmaxf(m, g_alpha[(size_t)e * 8 + lane]);
        }
    }

    float acc[16];
#pragma unroll
    for (int t = 0; t < 16; t++) acc[t] = 0.f;
    float dsum = 0.f;

    for (int i = beg; i < end; i++) {
        int e = g_perm[i];
        int src = ei[e];
        float w = 0.f;
        if (lane < 8) {
            w = expf(g_alpha[(size_t)e * 8 + lane] - m);
            dsum += w;
        }
        const float* pl = g_xl + (size_t)src * HC;
#pragma unroll
        for (int t = 0; t < 16; t++) {
            int h = t >> 1;
            float wh = __shfl_sync(0xffffffffu, w, h);
            acc[t] = fmaf(wh, pl[lane + 32 * t], acc[t]);
        }
    }

    float invd = (lane < 8 && dsum > 0.f) ? 1.f / dsum : 0.f;

    float sc = 0.f;
#pragma unroll
    for (int t = 0; t < 16; t++) {
        int k = lane + 32 * t;
        int h = t >> 1;
        float id = __shfl_sync(0xffffffffu, invd, h);
        float y = acc[t] * id + bias[k];
        y = fmaxf(y, 0.f);
        g_h[(size_t)n * HC + k] = y;
        sc = fmaf(y, pw[k], sc);
    }
    sc += __shfl_xor_sync(0xffffffffu, sc, 16);
    sc += __shfl_xor_sync(0xffffffffu, sc, 8);
    sc += __shfl_xor_sync(0xffffffffu, sc, 4);
    sc += __shfl_xor_sync(0xffffffffu, sc, 2);
    sc += __shfl_xor_sync(0xffffffffu, sc, 1);
    if (lane == 0) g_score[n] = tanhf(sc * g_rnorm);
}

// ------------------------- top-K selection per graph -------------------------
__global__ void __launch_bounds__(1024) k_topk() {
    __shared__ float s[NPG];
    int b = blockIdx.x, t = threadIdx.x;
    float v = g_score[b * NPG + t];
    s[t] = v;
    __syncthreads();
    int rank = 0;
#pragma unroll 4
    for (int j = 0; j < NPG; j++) {
        float o = s[j];
        rank += (o > v) || (o == v && j < t);
    }
    g_sel[b * NPG + t] = (rank < KSEL) ? 1 : 0;
}

// ------------------------- global max || mean pool over selected rows -------------------------
__global__ void __launch_bounds__(512) k_pool(float* __restrict__ out) {
    __shared__ float sv[NPG];
    __shared__ int sf[NPG];
    int b = blockIdx.x, ch = threadIdx.x;
    for (int j = ch; j < NPG; j += 512) {
        sf[j] = g_sel[b * NPG + j];
        sv[j] = g_score[b * NPG + j];
    }
    __syncthreads();
    float mx = -INFINITY, sm = 0.f;
    for (int j = 0; j < NPG; j++) {
        if (sf[j]) {
            float p = sv[j] * g_h[(size_t)(b * NPG + j) * HC + ch];
            mx = fmaxf(mx, p);
            sm += p;
        }
    }
    out[b * 1024 + ch] = mx;
    out[b * 1024 + 512 + ch] = sm * (1.f / (float)KSEL);
}

// ------------------------- launch -------------------------
extern "C" void kernel_launch(void* const* d_in, const int* in_sizes, int n_in,
                              void* d_out, int out_size) {
    const float* x    = (const float*)d_in[0];
    const float* ea   = (const float*)d_in[1];
    const float* Wl   = (const float*)d_in[2];
    const float* bl   = (const float*)d_in[3];
    const float* Wr   = (const float*)d_in[4];
    const float* br   = (const float*)d_in[5];
    const float* We   = (const float*)d_in[6];
    const float* att  = (const float*)d_in[7];
    const float* bias = (const float*)d_in[8];
    const float* pw   = (const float*)d_in[9];
    const int*   ei   = (const int*)d_in[10];
    float* out = (float*)d_out;

    k_rnorm<<<1, 512>>>(pw);
    k_zero<<<128, 256>>>();
    k_count<<<1024, 256>>>(ei);
    k_scanA<<<32, 1024>>>();
    k_scanB<<<1, 32>>>();
    k_scanC<<<32, 1024>>>();
    k_scatter<<<1024, 256>>>(ei);

    sgemm_x<<<dim3(NN / 128, 8), 256>>>(x, Wl, bl, Wr, br);
    k_egemm_alpha<<<dim3(NE / 128, 4), 256>>>(ea, We, att, ei);
    k_node<<<NN / 8, 256>>>(ei, bias, pw);
    k_topk<<<BG, 1024>>>();
    k_pool<<<BG, 512>>>(out);
}

// round 4
// speedup vs baseline: 2.3197x; 1.3367x over previous
#include <cuda_runtime.h>
#include <cuda_bf16.h>
#include <math.h>
#include <stdint.h>

#define NN    32768
#define NE    262144
#define BG    32
#define NPG   1024
#define KSEL  820
#define HH    8
#define CC    64
#define HC    512
#define NEG   0.2f

// ------------------------- scratch (static device memory) -------------------------
__device__ float g_xl[(size_t)NN * HC];       // 64 MB
__device__ float g_xr[(size_t)NN * HC];       // 64 MB
__device__ float g_alpha[(size_t)NE * HH];    // 8 MB
__device__ float g_h[(size_t)NN * HC];        // 64 MB
__device__ float g_score[NN];
__device__ int   g_cnt[NN];
__device__ int   g_off[NN + 1];
__device__ int   g_cur[NN];
__device__ int   g_perm[NE];
__device__ int   g_sel[NN];
__device__ int   g_bsum[32];
__device__ float g_rnorm;
// transposed+split weights: [n=0..1023][k=0..255] bf16
__device__ __align__(16) __nv_bfloat16 g_wthi[1024 * 256];
__device__ __align__(16) __nv_bfloat16 g_wtlo[1024 * 256];
// split x: [m][k=256] bf16
__device__ __align__(16) __nv_bfloat16 g_xhi[(size_t)NN * 256];
__device__ __align__(16) __nv_bfloat16 g_xlo[(size_t)NN * 256];

// ------------------------- helpers -------------------------
__device__ __forceinline__ uint32_t smem_u32(const void* p) {
    uint32_t a;
    asm("{ .reg .u64 t; cvta.to.shared.u64 t, %1; cvt.u32.u64 %0, t; }" : "=r"(a) : "l"(p));
    return a;
}
__device__ __forceinline__ uint32_t swz(uint32_t b) { return b ^ ((b >> 3) & 0x70); }

__device__ __forceinline__ void ldm4(uint32_t* r, uint32_t addr) {
    asm volatile("ldmatrix.sync.aligned.m8n8.x4.shared.b16 {%0,%1,%2,%3}, [%4];"
        : "=r"(r[0]), "=r"(r[1]), "=r"(r[2]), "=r"(r[3]) : "r"(addr));
}
__device__ __forceinline__ void mma_bf16(float* c, const uint32_t* a, uint32_t b0, uint32_t b1) {
    asm volatile("mma.sync.aligned.m16n8k16.row.col.f32.bf16.bf16.f32 "
        "{%0,%1,%2,%3},{%4,%5,%6,%7},{%8,%9},{%0,%1,%2,%3};"
        : "+f"(c[0]), "+f"(c[1]), "+f"(c[2]), "+f"(c[3])
        : "r"(a[0]), "r"(a[1]), "r"(a[2]), "r"(a[3]), "r"(b0), "r"(b1));
}

// ------------------------- small utility kernels -------------------------
__global__ void k_rnorm(const float* __restrict__ pw) {
    __shared__ float s[512];
    int t = threadIdx.x;
    float v = pw[t];
    s[t] = v * v;
    __syncthreads();
    for (int off = 256; off > 0; off >>= 1) {
        if (t < off) s[t] += s[t + off];
        __syncthreads();
    }
    if (t == 0) g_rnorm = rsqrtf(s[0]);
}

__global__ void k_zero() {
    int i = blockIdx.x * 256 + threadIdx.x;
    if (i < NN) g_cnt[i] = 0;
}

__global__ void k_count(const int* __restrict__ ei) {
    int e = blockIdx.x * 256 + threadIdx.x;
    if (e < NE) atomicAdd(&g_cnt[ei[NE + e]], 1);
}

__global__ void __launch_bounds__(1024) k_scanA() {
    __shared__ int s[1024];
    int b = blockIdx.x, t = threadIdx.x, gi = b * 1024 + t;
    int v = g_cnt[gi];
    s[t] = v;
    __syncthreads();
    for (int off = 1; off < 1024; off <<= 1) {
        int u = (t >= off) ? s[t - off] : 0;
        __syncthreads();
        s[t] += u;
        __syncthreads();
    }
    g_off[gi] = s[t] - v;
    if (t == 1023) g_bsum[b] = s[t];
}

__global__ void k_scanB() {
    int t = threadIdx.x;
    int v = g_bsum[t];
    int x = v;
    for (int off = 1; off < 32; off <<= 1) {
        int u = __shfl_up_sync(0xffffffffu, x, off);
        if (t >= off) x += u;
    }
    g_bsum[t] = x - v;
}

__global__ void __launch_bounds__(1024) k_scanC() {
    int b = blockIdx.x, t = threadIdx.x, gi = b * 1024 + t;
    int o = g_off[gi] + g_bsum[b];
    g_off[gi] = o;
    g_cur[gi] = o;
    if (gi == NN - 1) g_off[NN] = NE;
}

__global__ void k_scatter(const int* __restrict__ ei) {
    int e = blockIdx.x * 256 + threadIdx.x;
    if (e < NE) {
        int d = ei[NE + e];
        int p = atomicAdd(&g_cur[d], 1);
        g_perm[p] = e;
    }
}

// ------------------------- prep: weight transpose+split, x split -------------------------
__global__ void k_prepW(const float* __restrict__ Wl, const float* __restrict__ Wr) {
    int n = blockIdx.x;
    const float* W = (n < 512) ? Wl : Wr;
    int nc = (n < 512) ? n : n - 512;
    int k = threadIdx.x;
    float v = W[(size_t)k * HC + nc];
    __nv_bfloat16 h = __float2bfloat16(v);
    float lo = v - __bfloat162float(h);
    g_wthi[n * 256 + k] = h;
    g_wtlo[n * 256 + k] = __float2bfloat16(lo);
}

__global__ void k_prepX(const float* __restrict__ x) {
    size_t i = (size_t)(blockIdx.x * 256 + threadIdx.x) * 4;
    float4 v = *(const float4*)(x + i);
    __nv_bfloat162 h01 = __floats2bfloat162_rn(v.x, v.y);
    __nv_bfloat162 h23 = __floats2bfloat162_rn(v.z, v.w);
    float2 f01 = __bfloat1622float2(h01);
    float2 f23 = __bfloat1622float2(h23);
    __nv_bfloat162 l01 = __floats2bfloat162_rn(v.x - f01.x, v.y - f01.y);
    __nv_bfloat162 l23 = __floats2bfloat162_rn(v.z - f23.x, v.w - f23.y);
    uint2 hp, lp;
    hp.x = *(uint32_t*)&h01; hp.y = *(uint32_t*)&h23;
    lp.x = *(uint32_t*)&l01; lp.y = *(uint32_t*)&l23;
    *(uint2*)(g_xhi + i) = hp;
    *(uint2*)(g_xlo + i) = lp;
}

// ------------------------- split-bf16 tensor-core GEMM: [xl|xr] = x @ Wcat + bcat ----------
// grid (NN/128, 8). BM=128, BN=128, BK=64 (128B rows, sw128). 8 warps, warp tile 32x64.
// acc = hi*hi + hi*lo + lo*hi in fp32 via mma.sync.m16n8k16.
#define SA_HI 0
#define SA_LO 16384
#define SB_HI 32768
#define SB_LO 49152
#define MMA_SMEM 65536

__global__ void __launch_bounds__(256, 2) mma_x(const float* __restrict__ bl,
                                                const float* __restrict__ br) {
    extern __shared__ __align__(128) char sm[];
    uint32_t sb = smem_u32(sm);
    const int tid = threadIdx.x, lane = tid & 31, wid = tid >> 5;
    const int bm = blockIdx.x * 128;
    const int by = blockIdx.y;
    const char* pAh = (const char*)g_xhi + (size_t)bm * 512;
    const char* pAl = (const char*)g_xlo + (size_t)bm * 512;
    const char* pBh = (const char*)g_wthi + (size_t)by * 128 * 512;
    const char* pBl = (const char*)g_wtlo + (size_t)by * 128 * 512;
    const int wm = (wid & 3) * 32, wn = (wid >> 2) * 64;

    float acc[2][8][4];
#pragma unroll
    for (int a = 0; a < 2; a++)
#pragma unroll
        for (int b = 0; b < 8; b++)
#pragma unroll
            for (int c = 0; c < 4; c++) acc[a][b][c] = 0.f;

#pragma unroll 1
    for (int s = 0; s < 4; s++) {
        if (s) __syncthreads();
#pragma unroll
        for (int i = 0; i < 4; i++) {
            int c = tid + i * 256;
            int r = c >> 3, ch = c & 7;
            size_t go = (size_t)r * 512 + (size_t)s * 128 + ch * 16;
            uint32_t so = swz(r * 128 + ch * 16);
            *(uint4*)(sm + SA_HI + so) = *(const uint4*)(pAh + go);
            *(uint4*)(sm + SA_LO + so) = *(const uint4*)(pAl + go);
            *(uint4*)(sm + SB_HI + so) = *(const uint4*)(pBh + go);
            *(uint4*)(sm + SB_LO + so) = *(const uint4*)(pBl + go);
        }
        __syncthreads();

#pragma unroll
        for (int kk = 0; kk < 4; kk++) {
            uint32_t ah[2][4], al[2][4];
            const int arow = (lane & 7) + ((lane >> 3) & 1) * 8;
            const uint32_t acol = kk * 32 + (lane >> 4) * 16;
#pragma unroll
            for (int ma = 0; ma < 2; ma++) {
                uint32_t off = swz((wm + ma * 16 + arow) * 128 + acol);
                ldm4(ah[ma], sb + SA_HI + off);
                ldm4(al[ma], sb + SA_LO + off);
            }
            const int brow = (lane & 7) + (lane >> 4) * 8;
            const uint32_t bcol = kk * 32 + ((lane >> 3) & 1) * 16;
#pragma unroll
            for (int g = 0; g < 2; g++) {
                uint32_t bh[2][4], blo[2][4];
#pragma unroll
                for (int p = 0; p < 2; p++) {
                    uint32_t off = swz((wn + g * 32 + p * 16 + brow) * 128 + bcol);
                    ldm4(bh[p], sb + SB_HI + off);
                    ldm4(blo[p], sb + SB_LO + off);
                }
#pragma unroll
                for (int ma = 0; ma < 2; ma++)
#pragma unroll
                    for (int na = 0; na < 4; na++) {
                        int p = na >> 1, j = na & 1;
                        float* c = acc[ma][g * 4 + na];
                        mma_bf16(c, ah[ma], bh[p][j * 2], bh[p][j * 2 + 1]);
                        mma_bf16(c, ah[ma], blo[p][j * 2], blo[p][j * 2 + 1]);
                        mma_bf16(c, al[ma], bh[p][j * 2], bh[p][j * 2 + 1]);
                    }
            }
        }
    }

    // epilogue: add bias, write to g_xl/g_xr
#pragma unroll
    for (int ma = 0; ma < 2; ma++)
#pragma unroll
        for (int n = 0; n < 8; n++) {
            int nn = by * 128 + wn + n * 8 + (lane & 3) * 2;
            float* C = (nn < 512) ? g_xl : g_xr;
            const float* bias = (nn < 512) ? bl : br;
            int ncol = nn & 511;
            float b0 = bias[ncol], b1 = bias[ncol + 1];
            int r0 = bm + wm + ma * 16 + (lane >> 2);
            float2 v0 = {acc[ma][n][0] + b0, acc[ma][n][1] + b1};
            float2 v1 = {acc[ma][n][2] + b0, acc[ma][n][3] + b1};
            *(float2*)(C + (size_t)r0 * HC + ncol) = v0;
            *(float2*)(C + (size_t)(r0 + 8) * HC + ncol) = v1;
        }
}

// ------------------------- fused eproj GEMM + attention logits -------------------------
__global__ void __launch_bounds__(256) k_egemm_alpha(const float* __restrict__ EA,
                                                     const float* __restrict__ We,
                                                     const float* __restrict__ att,
                                                     const int* __restrict__ ei) {
    __shared__ float As[32][132];
    __shared__ float Bs[32][132];
    __shared__ int s_src[128];
    __shared__ int s_dst[128];
    const int tid = threadIdx.x;
    const int bm = blockIdx.x * 128;
    const int bn = blockIdx.y * 128;

#pragma unroll
    for (int i = 0; i < 4; i++) {
        int idx4 = tid + i * 256;
        int row = idx4 >> 3, c4 = idx4 & 7;
        float4 v = *(const float4*)(EA + (size_t)(bm + row) * 32 + c4 * 4);
        As[c4 * 4 + 0][row] = v.x;
        As[c4 * 4 + 1][row] = v.y;
        As[c4 * 4 + 2][row] = v.z;
        As[c4 * 4 + 3][row] = v.w;
    }
#pragma unroll
    for (int i = 0; i < 4; i++) {
        int idx4 = tid + i * 256;
        int krow = idx4 >> 5, c4 = idx4 & 31;
        *(float4*)(&Bs[krow][c4 * 4]) = *(const float4*)(We + (size_t)krow * HC + bn + c4 * 4);
    }
    if (tid < 128) s_src[tid] = ei[bm + tid];
    else           s_dst[tid - 128] = ei[NE + bm + tid - 128];
    __syncthreads();

    const int rm = (tid >> 4) * 8, cn = (tid & 15) * 8;
    float acc[8][8];
#pragma unroll
    for (int i = 0; i < 8; i++)
#pragma unroll
        for (int j = 0; j < 8; j++) acc[i][j] = 0.f;

#pragma unroll
    for (int k = 0; k < 32; k++) {
        float a[8], bb[8];
        *(float4*)(a)      = *(float4*)(&As[k][rm]);
        *(float4*)(a + 4)  = *(float4*)(&As[k][rm + 4]);
        *(float4*)(bb)     = *(float4*)(&Bs[k][cn]);
        *(float4*)(bb + 4) = *(float4*)(&Bs[k][cn + 4]);
#pragma unroll
        for (int i = 0; i < 8; i++)
#pragma unroll
            for (int j = 0; j < 8; j++) acc[i][j] = fmaf(a[i], bb[j], acc[i][j]);
    }

    float ra[8];
    *(float4*)(ra)     = *(const float4*)(att + bn + cn);
    *(float4*)(ra + 4) = *(const float4*)(att + bn + cn + 4);
    const int head = (bn >> 6) + ((tid & 15) >> 3);

#pragma unroll
    for (int i = 0; i < 8; i++) {
        int er = rm + i;
        const float* pl = g_xl + (size_t)s_src[er] * HC + bn + cn;
        const float* pr = g_xr + (size_t)s_dst[er] * HC + bn + cn;
        float l[8], r[8];
        *(float4*)(l)     = *(const float4*)(pl);
        *(float4*)(l + 4) = *(const float4*)(pl + 4);
        *(float4*)(r)     = *(const float4*)(pr);
        *(float4*)(r + 4) = *(const float4*)(pr + 4);
        float s = 0.f;
#pragma unroll
        for (int j = 0; j < 8; j++) {
            float v = acc[i][j] + l[j] + r[j];
            v = (v > 0.f) ? v : NEG * v;
            s = fmaf(v, ra[j], s);
        }
        s += __shfl_xor_sync(0xffffffffu, s, 4);
        s += __shfl_xor_sync(0xffffffffu, s, 2);
        s += __shfl_xor_sync(0xffffffffu, s, 1);
        if ((tid & 7) == 0) g_alpha[(size_t)(bm + er) * 8 + head] = s;
    }
}

// ------------------------- per-node softmax + aggregation + score -------------------------
__global__ void __launch_bounds__(256) k_node(const int* __restrict__ ei,
                                              const float* __restrict__ bias,
                                              const float* __restrict__ pw) {
    int tid = threadIdx.x;
    int warp = tid >> 5, lane = tid & 31;
    int n = blockIdx.x * 8 + warp;
    int beg = g_off[n], end = g_off[n + 1];

    float m = -INFINITY;
    if (lane < 8) {
        for (int i = beg; i < end; i++) {
            int e = g_perm[i];
            m = fmaxf(m, g_alpha[(size_t)e * 8 + lane]);
        }
    }

    float acc[16];
#pragma unroll
    for (int t = 0; t < 16; t++) acc[t] = 0.f;
    float dsum = 0.f;

    for (int i = beg; i < end; i++) {
        int e = g_perm[i];
        int src = ei[e];
        float w = 0.f;
        if (lane < 8) {
            w = expf(g_alpha[(size_t)e * 8 + lane] - m);
            dsum += w;
        }
        const float* pl = g_xl + (size_t)src * HC;
#pragma unroll
        for (int t = 0; t < 16; t++) {
            int h = t >> 1;
            float wh = __shfl_sync(0xffffffffu, w, h);
            acc[t] = fmaf(wh, pl[lane + 32 * t], acc[t]);
        }
    }

    float invd = (lane < 8 && dsum > 0.f) ? 1.f / dsum : 0.f;

    float sc = 0.f;
#pragma unroll
    for (int t = 0; t < 16; t++) {
        int k = lane + 32 * t;
        int h = t >> 1;
        float id = __shfl_sync(0xffffffffu, invd, h);
        float y = acc[t] * id + bias[k];
        y = fmaxf(y, 0.f);
        g_h[(size_t)n * HC + k] = y;
        sc = fmaf(y, pw[k], sc);
    }
    sc += __shfl_xor_sync(0xffffffffu, sc, 16);
    sc += __shfl_xor_sync(0xffffffffu, sc, 8);
    sc += __shfl_xor_sync(0xffffffffu, sc, 4);
    sc += __shfl_xor_sync(0xffffffffu, sc, 2);
    sc += __shfl_xor_sync(0xffffffffu, sc, 1);
    if (lane == 0) g_score[n] = tanhf(sc * g_rnorm);
}

// ------------------------- top-K selection per graph -------------------------
__global__ void __launch_bounds__(1024) k_topk() {
    __shared__ float s[NPG];
    int b = blockIdx.x, t = threadIdx.x;
    float v = g_score[b * NPG + t];
    s[t] = v;
    __syncthreads();
    int rank = 0;
#pragma unroll 4
    for (int j = 0; j < NPG; j++) {
        float o = s[j];
        rank += (o > v) || (o == v && j < t);
    }
    g_sel[b * NPG + t] = (rank < KSEL) ? 1 : 0;
}

// ------------------------- global max || mean pool over selected rows -------------------------
__global__ void __launch_bounds__(512) k_pool(float* __restrict__ out) {
    __shared__ float sv[NPG];
    __shared__ int sf[NPG];
    int b = blockIdx.x, ch = threadIdx.x;
    for (int j = ch; j < NPG; j += 512) {
        sf[j] = g_sel[b * NPG + j];
        sv[j] = g_score[b * NPG + j];
    }
    __syncthreads();
    float mx = -INFINITY, sm = 0.f;
    for (int j = 0; j < NPG; j++) {
        if (sf[j]) {
            float p = sv[j] * g_h[(size_t)(b * NPG + j) * HC + ch];
            mx = fmaxf(mx, p);
            sm += p;
        }
    }
    out[b * 1024 + ch] = mx;
    out[b * 1024 + 512 + ch] = sm * (1.f / (float)KSEL);
}

// ------------------------- launch -------------------------
extern "C" void kernel_launch(void* const* d_in, const int* in_sizes, int n_in,
                              void* d_out, int out_size) {
    const float* x    = (const float*)d_in[0];
    const float* ea   = (const float*)d_in[1];
    const float* Wl   = (const float*)d_in[2];
    const float* bl   = (const float*)d_in[3];
    const float* Wr   = (const float*)d_in[4];
    const float* br   = (const float*)d_in[5];
    const float* We   = (const float*)d_in[6];
    const float* att  = (const float*)d_in[7];
    const float* bias = (const float*)d_in[8];
    const float* pw   = (const float*)d_in[9];
    const int*   ei   = (const int*)d_in[10];
    float* out = (float*)d_out;

    static bool attr_set = false;
    if (!attr_set) {
        cudaFuncSetAttribute(mma_x, cudaFuncAttributeMaxDynamicSharedMemorySize, MMA_SMEM);
        attr_set = true;
    }

    k_rnorm<<<1, 512>>>(pw);
    k_zero<<<128, 256>>>();
    k_count<<<1024, 256>>>(ei);
    k_scanA<<<32, 1024>>>();
    k_scanB<<<1, 32>>>();
    k_scanC<<<32, 1024>>>();
    k_scatter<<<1024, 256>>>(ei);

    k_prepW<<<1024, 256>>>(Wl, Wr);
    k_prepX<<<8192, 256>>>(x);
    mma_x<<<dim3(NN / 128, 8), 256, MMA_SMEM>>>(bl, br);

    k_egemm_alpha<<<dim3(NE / 128, 4), 256>>>(ea, We, att, ei);
    k_node<<<NN / 8, 256>>>(ei, bias, pw);
    k_topk<<<BG, 1024>>>();
    k_pool<<<BG, 512>>>(out);
}

// round 5
// speedup vs baseline: 2.5721x; 1.1088x over previous
#include <cuda_runtime.h>
#include <cuda_bf16.h>
#include <math.h>
#include <stdint.h>

#define NN    32768
#define NE    262144
#define BG    32
#define NPG   1024
#define KSEL  820
#define HH    8
#define CC    64
#define HC    512
#define NEG   0.2f

// ------------------------- scratch (static device memory) -------------------------
__device__ float g_xl[(size_t)NN * HC];       // 64 MB
__device__ float g_xr[(size_t)NN * HC];       // 64 MB
__device__ float g_alpha[(size_t)NE * HH];    // 8 MB
__device__ float g_h[(size_t)NN * HC];        // 64 MB
__device__ float g_score[NN];
__device__ int   g_cnt[NN];
__device__ int   g_off[NN + 1];
__device__ int   g_cur[NN];
__device__ int   g_perm[NE];
__device__ int   g_sel[NN];
__device__ int   g_bsum[32];
__device__ float g_rnorm;
// transposed+split weights: [n=0..1023][k=0..255] bf16
__device__ __align__(16) __nv_bfloat16 g_wthi[1024 * 256];
__device__ __align__(16) __nv_bfloat16 g_wtlo[1024 * 256];
// transposed+split We: [n=0..511][k=0..31] bf16
__device__ __align__(16) __nv_bfloat16 g_wethi[512 * 32];
__device__ __align__(16) __nv_bfloat16 g_wetlo[512 * 32];
// split x: [m][k=256] bf16
__device__ __align__(16) __nv_bfloat16 g_xhi[(size_t)NN * 256];
__device__ __align__(16) __nv_bfloat16 g_xlo[(size_t)NN * 256];

// ------------------------- helpers -------------------------
__device__ __forceinline__ uint32_t smem_u32(const void* p) {
    uint32_t a;
    asm("{ .reg .u64 t; cvta.to.shared.u64 t, %1; cvt.u32.u64 %0, t; }" : "=r"(a) : "l"(p));
    return a;
}
__device__ __forceinline__ uint32_t swz(uint32_t b)   { return b ^ ((b >> 3) & 0x70); }  // SW128
__device__ __forceinline__ uint32_t swz64(uint32_t b) { return b ^ ((b >> 3) & 0x30); }  // SW64

__device__ __forceinline__ void ldm4(uint32_t* r, uint32_t addr) {
    asm volatile("ldmatrix.sync.aligned.m8n8.x4.shared.b16 {%0,%1,%2,%3}, [%4];"
        : "=r"(r[0]), "=r"(r[1]), "=r"(r[2]), "=r"(r[3]) : "r"(addr));
}
__device__ __forceinline__ void mma_bf16(float* c, const uint32_t* a, uint32_t b0, uint32_t b1) {
    asm volatile("mma.sync.aligned.m16n8k16.row.col.f32.bf16.bf16.f32 "
        "{%0,%1,%2,%3},{%4,%5,%6,%7},{%8,%9},{%0,%1,%2,%3};"
        : "+f"(c[0]), "+f"(c[1]), "+f"(c[2]), "+f"(c[3])
        : "r"(a[0]), "r"(a[1]), "r"(a[2]), "r"(a[3]), "r"(b0), "r"(b1));
}
__device__ __forceinline__ void split2(float a, float b, uint32_t& hi, uint32_t& lo) {
    __nv_bfloat162 h = __floats2bfloat162_rn(a, b);
    float2 hf = __bfloat1622float2(h);
    __nv_bfloat162 l = __floats2bfloat162_rn(a - hf.x, b - hf.y);
    hi = *(uint32_t*)&h;
    lo = *(uint32_t*)&l;
}

// ------------------------- small utility kernels -------------------------
__global__ void k_rnorm(const float* __restrict__ pw) {
    __shared__ float s[512];
    int t = threadIdx.x;
    float v = pw[t];
    s[t] = v * v;
    __syncthreads();
    for (int off = 256; off > 0; off >>= 1) {
        if (t < off) s[t] += s[t + off];
        __syncthreads();
    }
    if (t == 0) g_rnorm = rsqrtf(s[0]);
}

__global__ void k_zero() {
    int i = blockIdx.x * 256 + threadIdx.x;
    if (i < NN) g_cnt[i] = 0;
}

__global__ void k_count(const int* __restrict__ ei) {
    int e = blockIdx.x * 256 + threadIdx.x;
    if (e < NE) atomicAdd(&g_cnt[ei[NE + e]], 1);
}

__global__ void __launch_bounds__(1024) k_scanA() {
    __shared__ int s[1024];
    int b = blockIdx.x, t = threadIdx.x, gi = b * 1024 + t;
    int v = g_cnt[gi];
    s[t] = v;
    __syncthreads();
    for (int off = 1; off < 1024; off <<= 1) {
        int u = (t >= off) ? s[t - off] : 0;
        __syncthreads();
        s[t] += u;
        __syncthreads();
    }
    g_off[gi] = s[t] - v;
    if (t == 1023) g_bsum[b] = s[t];
}

__global__ void k_scanB() {
    int t = threadIdx.x;
    int v = g_bsum[t];
    int x = v;
    for (int off = 1; off < 32; off <<= 1) {
        int u = __shfl_up_sync(0xffffffffu, x, off);
        if (t >= off) x += u;
    }
    g_bsum[t] = x - v;
}

__global__ void __launch_bounds__(1024) k_scanC() {
    int b = blockIdx.x, t = threadIdx.x, gi = b * 1024 + t;
    int o = g_off[gi] + g_bsum[b];
    g_off[gi] = o;
    g_cur[gi] = o;
    if (gi == NN - 1) g_off[NN] = NE;
}

__global__ void k_scatter(const int* __restrict__ ei) {
    int e = blockIdx.x * 256 + threadIdx.x;
    if (e < NE) {
        int d = ei[NE + e];
        int p = atomicAdd(&g_cur[d], 1);
        g_perm[p] = e;
    }
}

// ------------------------- prep kernels -------------------------
__global__ void k_prepW(const float* __restrict__ Wl, const float* __restrict__ Wr) {
    int n = blockIdx.x;
    const float* W = (n < 512) ? Wl : Wr;
    int nc = (n < 512) ? n : n - 512;
    int k = threadIdx.x;
    float v = W[(size_t)k * HC + nc];
    __nv_bfloat16 h = __float2bfloat16(v);
    float lo = v - __bfloat162float(h);
    g_wthi[n * 256 + k] = h;
    g_wtlo[n * 256 + k] = __float2bfloat16(lo);
}

__global__ void k_prepWe(const float* __restrict__ We) {  // grid 512, block 32
    int n = blockIdx.x, k = threadIdx.x;
    float v = We[(size_t)k * HC + n];
    __nv_bfloat16 h = __float2bfloat16(v);
    float lo = v - __bfloat162float(h);
    g_wethi[n * 32 + k] = h;
    g_wetlo[n * 32 + k] = __float2bfloat16(lo);
}

__global__ void k_prepX(const float* __restrict__ x) {
    size_t i = (size_t)(blockIdx.x * 256 + threadIdx.x) * 4;
    float4 v = *(const float4*)(x + i);
    uint2 hp, lp;
    split2(v.x, v.y, hp.x, lp.x);
    split2(v.z, v.w, hp.y, lp.y);
    *(uint2*)(g_xhi + i) = hp;
    *(uint2*)(g_xlo + i) = lp;
}

// ------------------------- split-bf16 tensor-core GEMM: [xl|xr] = x @ Wcat + bcat ----------
#define SA_HI 0
#define SA_LO 16384
#define SB_HI 32768
#define SB_LO 49152
#define MMA_SMEM 65536

__global__ void __launch_bounds__(256, 2) mma_x(const float* __restrict__ bl,
                                                const float* __restrict__ br) {
    extern __shared__ __align__(128) char sm[];
    uint32_t sb = smem_u32(sm);
    const int tid = threadIdx.x, lane = tid & 31, wid = tid >> 5;
    const int bm = blockIdx.x * 128;
    const int by = blockIdx.y;
    const char* pAh = (const char*)g_xhi + (size_t)bm * 512;
    const char* pAl = (const char*)g_xlo + (size_t)bm * 512;
    const char* pBh = (const char*)g_wthi + (size_t)by * 128 * 512;
    const char* pBl = (const char*)g_wtlo + (size_t)by * 128 * 512;
    const int wm = (wid & 3) * 32, wn = (wid >> 2) * 64;

    float acc[2][8][4];
#pragma unroll
    for (int a = 0; a < 2; a++)
#pragma unroll
        for (int b = 0; b < 8; b++)
#pragma unroll
            for (int c = 0; c < 4; c++) acc[a][b][c] = 0.f;

#pragma unroll 1
    for (int s = 0; s < 4; s++) {
        if (s) __syncthreads();
#pragma unroll
        for (int i = 0; i < 4; i++) {
            int c = tid + i * 256;
            int r = c >> 3, ch = c & 7;
            size_t go = (size_t)r * 512 + (size_t)s * 128 + ch * 16;
            uint32_t so = swz(r * 128 + ch * 16);
            *(uint4*)(sm + SA_HI + so) = *(const uint4*)(pAh + go);
            *(uint4*)(sm + SA_LO + so) = *(const uint4*)(pAl + go);
            *(uint4*)(sm + SB_HI + so) = *(const uint4*)(pBh + go);
            *(uint4*)(sm + SB_LO + so) = *(const uint4*)(pBl + go);
        }
        __syncthreads();

#pragma unroll
        for (int kk = 0; kk < 4; kk++) {
            uint32_t ah[2][4], al[2][4];
            const int arow = (lane & 7) + ((lane >> 3) & 1) * 8;
            const uint32_t acol = kk * 32 + (lane >> 4) * 16;
#pragma unroll
            for (int ma = 0; ma < 2; ma++) {
                uint32_t off = swz((wm + ma * 16 + arow) * 128 + acol);
                ldm4(ah[ma], sb + SA_HI + off);
                ldm4(al[ma], sb + SA_LO + off);
            }
            const int brow = (lane & 7) + (lane >> 4) * 8;
            const uint32_t bcol = kk * 32 + ((lane >> 3) & 1) * 16;
#pragma unroll
            for (int g = 0; g < 2; g++) {
                uint32_t bh[2][4], blo[2][4];
#pragma unroll
                for (int p = 0; p < 2; p++) {
                    uint32_t off = swz((wn + g * 32 + p * 16 + brow) * 128 + bcol);
                    ldm4(bh[p], sb + SB_HI + off);
                    ldm4(blo[p], sb + SB_LO + off);
                }
#pragma unroll
                for (int ma = 0; ma < 2; ma++)
#pragma unroll
                    for (int na = 0; na < 4; na++) {
                        int p = na >> 1, j = na & 1;
                        float* c = acc[ma][g * 4 + na];
                        mma_bf16(c, ah[ma], bh[p][j * 2], bh[p][j * 2 + 1]);
                        mma_bf16(c, ah[ma], blo[p][j * 2], blo[p][j * 2 + 1]);
                        mma_bf16(c, al[ma], bh[p][j * 2], bh[p][j * 2 + 1]);
                    }
            }
        }
    }

#pragma unroll
    for (int ma = 0; ma < 2; ma++)
#pragma unroll
        for (int n = 0; n < 8; n++) {
            int nn = by * 128 + wn + n * 8 + (lane & 3) * 2;
            float* C = (nn < 512) ? g_xl : g_xr;
            const float* bias = (nn < 512) ? bl : br;
            int ncol = nn & 511;
            float b0 = bias[ncol], b1 = bias[ncol + 1];
            int r0 = bm + wm + ma * 16 + (lane >> 2);
            float2 v0 = {acc[ma][n][0] + b0, acc[ma][n][1] + b1};
            float2 v1 = {acc[ma][n][2] + b0, acc[ma][n][3] + b1};
            *(float2*)(C + (size_t)r0 * HC + ncol) = v0;
            *(float2*)(C + (size_t)(r0 + 8) * HC + ncol) = v1;
        }
}

// ------------------------- fused eproj MMA GEMM + attention logits -------------------------
// Tile: 128 edges x 128 channels, K=32 split-bf16 via mma.sync. grid (NE/128, 4).
__global__ void __launch_bounds__(256) k_egemm_alpha(const float* __restrict__ EA,
                                                     const float* __restrict__ att,
                                                     const int* __restrict__ ei) {
    __shared__ __align__(128) char sAh[8192];
    __shared__ __align__(128) char sAl[8192];
    __shared__ __align__(128) char sBh[8192];
    __shared__ __align__(128) char sBl[8192];
    __shared__ int s_src[128];
    __shared__ int s_dst[128];
    const int tid = threadIdx.x, lane = tid & 31, wid = tid >> 5;
    const int bm = blockIdx.x * 128;   // edge base
    const int bn = blockIdx.y * 128;   // channel base
    const int wm = (wid & 3) * 32, wn = (wid >> 2) * 64;

    // load + split A (edge_attr): thread -> row=tid>>1, half 16 floats
    {
        int row = tid >> 1, half = tid & 1;
        const float* p = EA + (size_t)(bm + row) * 32 + half * 16;
        uint32_t hi[8], lo[8];
#pragma unroll
        for (int q = 0; q < 4; q++) {
            float4 v = *(const float4*)(p + q * 4);
            split2(v.x, v.y, hi[q * 2], lo[q * 2]);
            split2(v.z, v.w, hi[q * 2 + 1], lo[q * 2 + 1]);
        }
        uint32_t b0 = swz64(row * 64 + half * 32);
        uint32_t b1 = swz64(row * 64 + half * 32 + 16);
        *(uint4*)(sAh + b0) = *(uint4*)(hi);
        *(uint4*)(sAh + b1) = *(uint4*)(hi + 4);
        *(uint4*)(sAl + b0) = *(uint4*)(lo);
        *(uint4*)(sAl + b1) = *(uint4*)(lo + 4);
    }
    // load B (We^T split): 128 rows x 32 bf16
    {
        int nl = tid >> 1, half = tid & 1;
        const char* ph = (const char*)(g_wethi + (size_t)(bn + nl) * 32 + half * 16);
        const char* pl = (const char*)(g_wetlo + (size_t)(bn + nl) * 32 + half * 16);
        uint32_t b0 = swz64(nl * 64 + half * 32);
        uint32_t b1 = swz64(nl * 64 + half * 32 + 16);
        *(uint4*)(sBh + b0) = *(const uint4*)(ph);
        *(uint4*)(sBh + b1) = *(const uint4*)(ph + 16);
        *(uint4*)(sBl + b0) = *(const uint4*)(pl);
        *(uint4*)(sBl + b1) = *(const uint4*)(pl + 16);
    }
    if (tid < 128) s_src[tid] = ei[bm + tid];
    else           s_dst[tid - 128] = ei[NE + bm + tid - 128];
    __syncthreads();

    uint32_t sbAh = smem_u32(sAh), sbAl = smem_u32(sAl);
    uint32_t sbBh = smem_u32(sBh), sbBl = smem_u32(sBl);

    float acc[2][8][4];
#pragma unroll
    for (int a = 0; a < 2; a++)
#pragma unroll
        for (int b = 0; b < 8; b++)
#pragma unroll
            for (int c = 0; c < 4; c++) acc[a][b][c] = 0.f;

#pragma unroll
    for (int kk = 0; kk < 2; kk++) {
        uint32_t ah[2][4], al[2][4];
        const int arow = (lane & 7) + ((lane >> 3) & 1) * 8;
        const uint32_t acol = kk * 32 + (lane >> 4) * 16;
#pragma unroll
        for (int ma = 0; ma < 2; ma++) {
            uint32_t off = swz64((wm + ma * 16 + arow) * 64 + acol);
            ldm4(ah[ma], sbAh + off);
            ldm4(al[ma], sbAl + off);
        }
        const int brow = (lane & 7) + (lane >> 4) * 8;
        const uint32_t bcol = kk * 32 + ((lane >> 3) & 1) * 16;
#pragma unroll
        for (int g = 0; g < 2; g++) {
            uint32_t bh[2][4], blo[2][4];
#pragma unroll
            for (int p = 0; p < 2; p++) {
                uint32_t off = swz64((wn + g * 32 + p * 16 + brow) * 64 + bcol);
                ldm4(bh[p], sbBh + off);
                ldm4(blo[p], sbBl + off);
            }
#pragma unroll
            for (int ma = 0; ma < 2; ma++)
#pragma unroll
                for (int na = 0; na < 4; na++) {
                    int p = na >> 1, j = na & 1;
                    float* c = acc[ma][g * 4 + na];
                    mma_bf16(c, ah[ma], bh[p][j * 2], bh[p][j * 2 + 1]);
                    mma_bf16(c, ah[ma], blo[p][j * 2], blo[p][j * 2 + 1]);
                    mma_bf16(c, al[ma], bh[p][j * 2], bh[p][j * 2 + 1]);
                }
        }
    }

    // epilogue: gather xl/xr, leaky, dot att, reduce to alpha[e, head]
    const int c0 = wn + (lane & 3) * 2;
    const int head = (bn + wn) >> 6;
    float2 attv[8];
#pragma unroll
    for (int n = 0; n < 8; n++) attv[n] = *(const float2*)(att + bn + c0 + n * 8);

#pragma unroll
    for (int ma = 0; ma < 2; ma++) {
#pragma unroll
        for (int half = 0; half < 2; half++) {
            int r = wm + ma * 16 + (lane >> 2) + half * 8;
            const float* pl = g_xl + (size_t)s_src[r] * HC + bn + c0;
            const float* pr = g_xr + (size_t)s_dst[r] * HC + bn + c0;
            float s = 0.f;
#pragma unroll
            for (int n = 0; n < 8; n++) {
                float2 l = *(const float2*)(pl + n * 8);
                float2 rr = *(const float2*)(pr + n * 8);
                float v0 = acc[ma][n][half * 2 + 0] + l.x + rr.x;
                float v1 = acc[ma][n][half * 2 + 1] + l.y + rr.y;
                v0 = (v0 > 0.f) ? v0 : NEG * v0;
                v1 = (v1 > 0.f) ? v1 : NEG * v1;
                s = fmaf(v0, attv[n].x, s);
                s = fmaf(v1, attv[n].y, s);
            }
            s += __shfl_xor_sync(0xffffffffu, s, 1);
            s += __shfl_xor_sync(0xffffffffu, s, 2);
            if ((lane & 3) == 0) g_alpha[(size_t)(bm + r) * 8 + head] = s;
        }
    }
}

// ------------------------- per-node softmax + aggregation + score -------------------------
__global__ void __launch_bounds__(256) k_node(const int* __restrict__ ei,
                                              const float* __restrict__ bias,
                                              const float* __restrict__ pw) {
    int tid = threadIdx.x;
    int warp = tid >> 5, lane = tid & 31;
    int n = blockIdx.x * 8 + warp;
    int beg = g_off[n], end = g_off[n + 1];

    float m = -INFINITY;
    if (lane < 8) {
        for (int i = beg; i < end; i++) {
            int e = g_perm[i];
            m = fmaxf(m, g_alpha[(size_t)e * 8 + lane]);
        }
    }

    float acc[16];
#pragma unroll
    for (int t = 0; t < 16; t++) acc[t] = 0.f;
    float dsum = 0.f;

    for (int i = beg; i < end; i++) {
        int e = g_perm[i];
        int src = ei[e];
        float w = 0.f;
        if (lane < 8) {
            w = expf(g_alpha[(size_t)e * 8 + lane] - m);
            dsum += w;
        }
        const float* pl = g_xl + (size_t)src * HC;
#pragma unroll
        for (int t = 0; t < 16; t++) {
            int h = t >> 1;
            float wh = __shfl_sync(0xffffffffu, w, h);
            acc[t] = fmaf(wh, pl[lane + 32 * t], acc[t]);
        }
    }

    float invd = (lane < 8 && dsum > 0.f) ? 1.f / dsum : 0.f;

    float sc = 0.f;
#pragma unroll
    for (int t = 0; t < 16; t++) {
        int k = lane + 32 * t;
        int h = t >> 1;
        float id = __shfl_sync(0xffffffffu, invd, h);
        float y = acc[t] * id + bias[k];
        y = fmaxf(y, 0.f);
        g_h[(size_t)n * HC + k] = y;
        sc = fmaf(y, pw[k], sc);
    }
    sc += __shfl_xor_sync(0xffffffffu, sc, 16);
    sc += __shfl_xor_sync(0xffffffffu, sc, 8);
    sc += __shfl_xor_sync(0xffffffffu, sc, 4);
    sc += __shfl_xor_sync(0xffffffffu, sc, 2);
    sc += __shfl_xor_sync(0xffffffffu, sc, 1);
    if (lane == 0) g_score[n] = tanhf(sc * g_rnorm);
}

// ------------------------- top-K selection per graph -------------------------
__global__ void __launch_bounds__(1024) k_topk() {
    __shared__ float s[NPG];
    int b = blockIdx.x, t = threadIdx.x;
    float v = g_score[b * NPG + t];
    s[t] = v;
    __syncthreads();
    int rank = 0;
#pragma unroll 4
    for (int j = 0; j < NPG; j++) {
        float o = s[j];
        rank += (o > v) || (o == v && j < t);
    }
    g_sel[b * NPG + t] = (rank < KSEL) ? 1 : 0;
}

// ------------------------- global max || mean pool over selected rows -------------------------
__global__ void __launch_bounds__(512) k_pool(float* __restrict__ out) {
    __shared__ float sv[NPG];
    __shared__ int sf[NPG];
    int b = blockIdx.x, ch = threadIdx.x;
    for (int j = ch; j < NPG; j += 512) {
        sf[j] = g_sel[b * NPG + j];
        sv[j] = g_score[b * NPG + j];
    }
    __syncthreads();
    float mx = -INFINITY, sm = 0.f;
    for (int j = 0; j < NPG; j++) {
        if (sf[j]) {
            float p = sv[j] * g_h[(size_t)(b * NPG + j) * HC + ch];
            mx = fmaxf(mx, p);
            sm += p;
        }
    }
    out[b * 1024 + ch] = mx;
    out[b * 1024 + 512 + ch] = sm * (1.f / (float)KSEL);
}

// ------------------------- launch -------------------------
extern "C" void kernel_launch(void* const* d_in, const int* in_sizes, int n_in,
                              void* d_out, int out_size) {
    const float* x    = (const float*)d_in[0];
    const float* ea   = (const float*)d_in[1];
    const float* Wl   = (const float*)d_in[2];
    const float* bl   = (const float*)d_in[3];
    const float* Wr   = (const float*)d_in[4];
    const float* br   = (const float*)d_in[5];
    const float* We   = (const float*)d_in[6];
    const float* att  = (const float*)d_in[7];
    const float* bias = (const float*)d_in[8];
    const float* pw   = (const float*)d_in[9];
    const int*   ei   = (const int*)d_in[10];
    float* out = (float*)d_out;

    static bool attr_set = false;
    if (!attr_set) {
        cudaFuncSetAttribute(mma_x, cudaFuncAttributeMaxDynamicSharedMemorySize, MMA_SMEM);
        attr_set = true;
    }

    k_rnorm<<<1, 512>>>(pw);
    k_zero<<<128, 256>>>();
    k_count<<<1024, 256>>>(ei);
    k_scanA<<<32, 1024>>>();
    k_scanB<<<1, 32>>>();
    k_scanC<<<32, 1024>>>();
    k_scatter<<<1024, 256>>>(ei);

    k_prepW<<<1024, 256>>>(Wl, Wr);
    k_prepWe<<<512, 32>>>(We);
    k_prepX<<<8192, 256>>>(x);
    mma_x<<<dim3(NN / 128, 8), 256, MMA_SMEM>>>(bl, br);

    k_egemm_alpha<<<dim3(NE / 128, 4), 256>>>(ea, att, ei);
    k_node<<<NN / 8, 256>>>(ei, bias, pw);
    k_topk<<<BG, 1024>>>();
    k_pool<<<BG, 512>>>(out);
}